// round 17
// baseline (speedup 1.0000x reference)
#include <cuda_runtime.h>

// Problem constants (match reference)
#define NIMG     2
#define VOL      (96*96*96)          // 884736, divisible by 8
#define V8       (VOL/8)             // 110592 = 864 blocks * 128 threads
#define EPSF     1e-8f

// full cubic B-spline (slow path only)
__device__ __forceinline__ float bspline(float d) {
    float ad  = fabsf(d);
    float ad2 = ad * ad;
    float w_in  = (3.0f * ad2 * ad - 6.0f * ad2 + 4.0f) * (1.0f / 6.0f);
    float u     = 2.0f - ad;
    float w_out = u * u * u * (1.0f / 6.0f);
    return ad < 1.0f ? w_in : (ad < 2.0f ? w_out : 0.0f);
}

// per-voxel density pair: bit-exact critical chain + fast/slow path (R13-verified)
__device__ __forceinline__ void density_pair(float a, float c, float& r0, float& r1) {
    float mn = fminf(a, c), mx = fmaxf(a, c);
    float bw   = __fmul_rn(__fsub_rn(mx, mn), 0.0625f);   // (max-min)/16
    float pmin = __fsub_rn(mn, __fmul_rn(bw, 2.0f));      // pad_min
    float bws  = fmaxf(bw, EPSF);                         // clip(bin_width, EPS)
    float rcp  = __frcp_rn(bws);                          // reference divide = rcp.rn+mul.rn
    float pos0 = __fmul_rn(__fsub_rn(a, pmin), rcp);
    float pos1 = __fmul_rn(__fsub_rn(c, pmin), rcp);

    float lo = fminf(pos0, pos1), hi = fmaxf(pos0, pos1);

    if (lo >= 1.99f && hi <= 18.01f) {
        // FAST PATH: gather clip identity, d=frac in [0,1), windows disjoint,
        // denominator = 2 (partition of unity). half-density = t^2(0.25t-0.5)+1/3
        float t0 = __fsub_rn(pos0, floorf(pos0));
        float t1 = __fsub_rn(pos1, floorf(pos1));
        r0 = fmaf(t0 * t0, fmaf(0.25f, t0, -0.5f), 1.0f / 3.0f);
        r1 = fmaf(t1 * t1, fmaf(0.25f, t1, -0.5f), 1.0f / 3.0f);
    } else {
        // SLOW PATH (degenerate tiny-range voxels): full reference math
        float f0 = floorf(pos0), f1 = floorf(pos1);
        float bi0 = fminf(fmaxf(f0, 2.0f), 17.0f);
        float bi1 = fminf(fmaxf(f1, 2.0f), 17.0f);
        int   i0 = (int)bi0,  i1 = (int)bi1;
        int   g0 = (int)fminf(fmaxf(f0, 0.0f), 19.0f);
        int   g1 = (int)fminf(fmaxf(f1, 0.0f), 19.0f);
        float s = 0.0f;
#pragma unroll
        for (int r = 0; r < 4; r++) {
            s += bspline(pos0 - (bi0 - 1.0f + (float)r));
            s += bspline(pos1 - (bi1 - 1.0f + (float)r));
        }
        float h0 = 0.0f, h1 = 0.0f;
        if (g0 >= i0 - 1 && g0 <= i0 + 2) h0 += bspline(pos0 - (float)g0);
        if (g0 >= i1 - 1 && g0 <= i1 + 2) h0 += bspline(pos1 - (float)g0);
        if (g1 >= i0 - 1 && g1 <= i0 + 2) h1 += bspline(pos0 - (float)g1);
        if (g1 >= i1 - 1 && g1 <= i1 + 2) h1 += bspline(pos1 - (float)g1);
        float dinv = 1.0f / fmaxf(s, EPSF);
        r0 = h0 * dinv;
        r1 = h1 * dinv;
    }
}

__global__ void __launch_bounds__(128)
parzen_density_kernel(const float* __restrict__ img,
                      const float* __restrict__ mask,
                      float* __restrict__ out)
{
    int v8  = blockIdx.x * 128 + threadIdx.x;     // [0, V8)
    int b   = blockIdx.y;                         // batch
    int base = b * (NIMG * VOL) + v8 * 8;

    // 12 front-batched 16B L2-only loads (.cg): working set >> L1, L2-resident
    float4 x0a = __ldcg((const float4*)(img  + base));
    float4 x0b = __ldcg((const float4*)(img  + base + 4));
    float4 x1a = __ldcg((const float4*)(img  + base + VOL));
    float4 x1b = __ldcg((const float4*)(img  + base + VOL + 4));
    float4 m0a = __ldcg((const float4*)(mask + base));
    float4 m0b = __ldcg((const float4*)(mask + base + 4));
    float4 m1a = __ldcg((const float4*)(mask + base + VOL));
    float4 m1b = __ldcg((const float4*)(mask + base + VOL + 4));

    float xa[8] = {x0a.x, x0a.y, x0a.z, x0a.w, x0b.x, x0b.y, x0b.z, x0b.w};
    float xb[8] = {x1a.x, x1a.y, x1a.z, x1a.w, x1b.x, x1b.y, x1b.z, x1b.w};
    float ma[8] = {m0a.x, m0a.y, m0a.z, m0a.w, m0b.x, m0b.y, m0b.z, m0b.w};
    float mb[8] = {m1a.x, m1a.y, m1a.z, m1a.w, m1b.x, m1b.y, m1b.z, m1b.w};
    float oa[8], ob[8];

#pragma unroll
    for (int l = 0; l < 8; l++) {
        float r0, r1;
        density_pair(xa[l], xb[l], r0, r1);
        oa[l] = (ma[l] != 0.0f) ? r0 : 0.0f;
        ob[l] = (mb[l] != 0.0f) ? r1 : 0.0f;
    }

    *(float4*)(out + base)           = make_float4(oa[0], oa[1], oa[2], oa[3]);
    *(float4*)(out + base + 4)       = make_float4(oa[4], oa[5], oa[6], oa[7]);
    *(float4*)(out + base + VOL)     = make_float4(ob[0], ob[1], ob[2], ob[3]);
    *(float4*)(out + base + VOL + 4) = make_float4(ob[4], ob[5], ob[6], ob[7]);
}

extern "C" void kernel_launch(void* const* d_in, const int* in_sizes, int n_in,
                              void* d_out, int out_size)
{
    const float* img  = (const float*)d_in[0];   // [2,2,1,96,96,96] f32
    const float* mask = (const float*)d_in[1];   // [2,2,96,96,96]   f32
    float* out = (float*)d_out;                  // [2,2,96,96,96]   f32

    dim3 grid(V8 / 128, 2);                      // 864 x 2 = 1728 blocks of 128 thr
    parzen_density_kernel<<<grid, 128>>>(img, mask, out);
}